// round 4
// baseline (speedup 1.0000x reference)
#include <cuda_runtime.h>
#include <cstdint>
#include <cstddef>

#define B_ 4
#define KNB 32

// ---------------- device scratch (no cudaMalloc allowed) ----------------
__device__ float g_feat[(size_t)4 * 195 * 16384];
__device__ float g_Y [(size_t)4 * 192 * 65536];
__device__ float g_Y2[(size_t)4 * 192 * 65536];
__device__ int   g_idx1[4 * 2048];
__device__ int   g_idx2[4 * 512];
__device__ int   g_gidx[4 * 2048 * 32];
__device__ float g_cp1[4 * 2048 * 3];
__device__ float g_cp2[4 * 512 * 3];
__device__ float g_stats[4 * 384 * 2];
__device__ float g_xsum[4 * 384];
__device__ float g_rmax1[(size_t)4 * 192 * 2048];
__device__ float g_rmax2[(size_t)4 * 192 * 2048];
__device__ float g_gate[4 * 384];
__device__ float g_Wa[4 * 384 * 384];
__device__ float g_Wb[4 * 384 * 384];
__device__ float g_bias[(size_t)4 * 192 * 2048];
__device__ float g_f1[(size_t)4 * 192 * 2048];

// ---------------- packed f32x2 helpers (exact per-half rn) ----------------
__device__ __forceinline__ unsigned long long packf2(float lo, float hi) {
    unsigned long long r;
    asm("mov.b64 %0, {%1, %2};" : "=l"(r) : "f"(lo), "f"(hi));
    return r;
}
__device__ __forceinline__ void unpackf2(unsigned long long v, float& lo, float& hi) {
    asm("mov.b64 {%0, %1}, %2;" : "=f"(lo), "=f"(hi) : "l"(v));
}
__device__ __forceinline__ unsigned long long addx2(unsigned long long a, unsigned long long b) {
    unsigned long long r;
    asm("add.rn.f32x2 %0, %1, %2;" : "=l"(r) : "l"(a), "l"(b));
    return r;
}
__device__ __forceinline__ unsigned long long mulx2(unsigned long long a, unsigned long long b) {
    unsigned long long r;
    asm("mul.rn.f32x2 %0, %1, %2;" : "=l"(r) : "l"(a), "l"(b));
    return r;
}

// ============================================================================
// FPS v4 — fmax-only tracking + winner-only index scan; REDUX; 1 barrier/iter.
// ============================================================================
template <int N, int M, int T>
__global__ void fps_kernel(const float* __restrict__ p,
                           int* __restrict__ idx_out,
                           float* __restrict__ cp_out) {
    extern __shared__ float sm[];
    float* sx = sm;
    float* sy = sm + N;
    float* sz = sm + 2 * N;
    constexpr int PPT = N / T;
    constexpr int NP  = PPT / 2;
    constexpr int NW  = T / 32;
    __shared__ unsigned sval[2][NW];
    __shared__ int      sidx[2][NW];

    const int b = blockIdx.x;
    const int t = threadIdx.x;
    const int lane = t & 31, w = t >> 5;
    const float* pb = p + (size_t)b * N * 3;

    for (int i = t; i < N; i += T) {
        sx[i] = pb[i * 3 + 0];
        sy[i] = pb[i * 3 + 1];
        sz[i] = pb[i * 3 + 2];
    }
    __syncthreads();

    unsigned long long pxp[NP], pyp[NP], pzp[NP];
    float dist[PPT];
#pragma unroll
    for (int i = 0; i < NP; i++) {
        int g0 = t * PPT + 2 * i;
        pxp[i] = packf2(sx[g0], sx[g0 + 1]);
        pyp[i] = packf2(sy[g0], sy[g0 + 1]);
        pzp[i] = packf2(sz[g0], sz[g0 + 1]);
        dist[2 * i] = 1e10f; dist[2 * i + 1] = 1e10f;
    }

    float lx = sx[0], ly = sy[0], lz = sz[0];
    if (t == 0) {
        idx_out[b * M] = 0;
        cp_out[(size_t)b * M * 3 + 0] = lx;
        cp_out[(size_t)b * M * 3 + 1] = ly;
        cp_out[(size_t)b * M * 3 + 2] = lz;
    }

    for (int j = 1; j < M; j++) {
        unsigned long long nx = packf2(-lx, -lx);
        unsigned long long ny = packf2(-ly, -ly);
        unsigned long long nz = packf2(-lz, -lz);
        float bv = -1.0f;
#pragma unroll
        for (int i = 0; i < NP; i++) {
            unsigned long long dx = addx2(pxp[i], nx);
            unsigned long long dy = addx2(pyp[i], ny);
            unsigned long long dz = addx2(pzp[i], nz);
            unsigned long long s  = addx2(addx2(mulx2(dx, dx), mulx2(dy, dy)), mulx2(dz, dz));
            float d0, d1; unpackf2(s, d0, d1);
            float m0 = fminf(dist[2 * i], d0);     dist[2 * i] = m0;
            float m1 = fminf(dist[2 * i + 1], d1); dist[2 * i + 1] = m1;
            bv = fmaxf(bv, fmaxf(m0, m1));
        }
        unsigned vb = __float_as_uint(bv);               // bv >= 0: bits monotone
        unsigned wm = __reduce_max_sync(0xffffffffu, vb);
        int cand = 0x7fffffff;
        if (vb == wm) {                                   // winner(s) only: find first idx
#pragma unroll
            for (int i = 0; i < PPT; i++)
                if (cand == 0x7fffffff && __float_as_uint(dist[i]) == vb)
                    cand = t * PPT + i;
        }
        int wi = __reduce_min_sync(0xffffffffu, cand);
        int par = j & 1;
        if (lane == 0) { sval[par][w] = wm; sidx[par][w] = wi; }
        __syncthreads();
        unsigned v2 = (lane < NW) ? sval[par][lane] : 0u;
        unsigned m2 = __reduce_max_sync(0xffffffffu, v2);
        int c2 = (lane < NW && v2 == m2) ? sidx[par][lane] : 0x7fffffff;
        int ii = __reduce_min_sync(0xffffffffu, c2);
        lx = sx[ii]; ly = sy[ii]; lz = sz[ii];
        if (t == 0) {
            idx_out[b * M + j] = ii;
            cp_out[((size_t)b * M + j) * 3 + 0] = lx;
            cp_out[((size_t)b * M + j) * 3 + 1] = ly;
            cp_out[((size_t)b * M + j) * 3 + 2] = lz;
        }
    }
}

// ============================================================================
// Ball query (exact fp32 rn threshold math)
// ============================================================================
__global__ void ballquery_kernel(const float* __restrict__ cp,
                                 const float* __restrict__ p,
                                 int* __restrict__ gidx, int N, int M) {
    int wid  = (blockIdx.x * blockDim.x + threadIdx.x) >> 5;
    int lane = threadIdx.x & 31;
    if (wid >= B_ * M) return;
    int b = wid / M, m = wid % M;

    const float* c = cp + ((size_t)b * M + m) * 3;
    float cx = c[0], cy = c[1], cz = c[2];
    const float* pb = p + (size_t)b * N * 3;
    int* row = gidx + ((size_t)b * M + m) * KNB;

    int cnt = 0;
    int firstIdx = -1;
    for (int base = 0; base < N && cnt < KNB; base += 32) {
        int i = base + lane;
        float dx = pb[i * 3 + 0] - cx;
        float dy = pb[i * 3 + 1] - cy;
        float dz = pb[i * 3 + 2] - cz;
        float d2 = __fadd_rn(__fadd_rn(__fmul_rn(dx, dx), __fmul_rn(dy, dy)),
                             __fmul_rn(dz, dz));
        bool within = d2 < 0.01f;
        unsigned ball = __ballot_sync(0xffffffffu, within);
        if (within) {
            int pos = cnt + __popc(ball & ((1u << lane) - 1u));
            if (pos < KNB) row[pos] = i;
        }
        if (firstIdx < 0 && ball) firstIdx = base + (__ffs(ball) - 1);
        cnt += __popc(ball);
    }
    if (cnt > KNB) cnt = KNB;
    if (firstIdx < 0) firstIdx = 0;
    for (int pos = cnt + lane; pos < KNB; pos += 32) row[pos] = firstIdx;
}

// ============================================================================
// Stage0 conv1 fused: gather + (p-cp, f-cf) + 192x6 direct conv.
// ============================================================================
__global__ void conv1s0_kernel(const float* __restrict__ p,
                               const float* __restrict__ cp,
                               const float* __restrict__ f,
                               const int* __restrict__ gidx,
                               const int* __restrict__ cidx,
                               const float* __restrict__ W,
                               float* __restrict__ Y) {
    __shared__ float ws[192 * 6];
    int b = blockIdx.y;
    int tid = threadIdx.x;
    for (int i = tid; i < 192 * 6; i += 256) ws[i] = W[i];
    int mk = blockIdx.x * 256 + tid;
    int m = mk >> 5;
    int g = gidx[((size_t)b * 2048 + m) * 32 + (mk & 31)];
    int ci = cidx[b * 2048 + m];
    __syncthreads();

    float v[6];
    const float* pg = p + ((size_t)b * 8192 + g) * 3;
    const float* cm = cp + ((size_t)b * 2048 + m) * 3;
    v[0] = pg[0] - cm[0]; v[1] = pg[1] - cm[1]; v[2] = pg[2] - cm[2];
    const float* fb = f + (size_t)b * 3 * 8192;
    v[3] = fb[g] - fb[ci];
    v[4] = fb[8192 + g] - fb[8192 + ci];
    v[5] = fb[16384 + g] - fb[16384 + ci];

    float* yb = Y + (size_t)b * 192 * 65536 + mk;
#pragma unroll 4
    for (int o = 0; o < 192; o++) {
        const float* wr = ws + o * 6;
        float a = wr[0] * v[0] + wr[1] * v[1] + wr[2] * v[2]
                + wr[3] * v[3] + wr[4] * v[4] + wr[5] * v[5];
        yb[(size_t)o * 65536] = a;
    }
}

// ============================================================================
// Build feat for stage1 (C=192)
// ============================================================================
__global__ void build_feat_kernel(const float* __restrict__ p,
                                  const float* __restrict__ cp,
                                  const float* __restrict__ f,
                                  const int* __restrict__ gidx,
                                  const int* __restrict__ cidx,
                                  float* __restrict__ feat,
                                  int N, int M, int C) {
    __shared__ int sg[KNB];
    int b = blockIdx.y, m = blockIdx.x, tid = threadIdx.x;
    if (tid < KNB) sg[tid] = gidx[((size_t)b * M + m) * KNB + tid];
    __syncthreads();
    int ci = cidx[b * M + m];
    size_t MK = (size_t)M * KNB;
    size_t fbase = (size_t)b * (3 + C) * MK + (size_t)m * KNB;

    if (tid < 3 * KNB) {
        int c = tid / KNB, k = tid % KNB;
        int g = sg[k];
        feat[fbase + (size_t)c * MK + k] =
            p[((size_t)b * N + g) * 3 + c] - cp[((size_t)b * M + m) * 3 + c];
    }
    for (int t = tid; t < C * KNB; t += blockDim.x) {
        int c = t / KNB, k = t % KNB;
        int g = sg[k];
        const float* frow = f + ((size_t)b * C + c) * N;
        feat[fbase + (size_t)(3 + c) * MK + k] = frow[g] - frow[ci];
    }
}

// ============================================================================
// TF32 MMA GEMM (3-term split, fp32-grade) + fused sum/sumsq epilogue stats.
// ============================================================================
__device__ __forceinline__ unsigned f2tf(float x) {
    unsigned r; asm("cvt.rna.tf32.f32 %0, %1;" : "=r"(r) : "f"(x)); return r;
}
__device__ __forceinline__ void mma8(float* d, const unsigned* a, const unsigned* b) {
    asm volatile("mma.sync.aligned.m16n8k8.row.col.f32.tf32.tf32.f32 "
                 "{%0,%1,%2,%3}, {%4,%5,%6,%7}, {%8,%9}, {%0,%1,%2,%3};"
                 : "+f"(d[0]), "+f"(d[1]), "+f"(d[2]), "+f"(d[3])
                 : "r"(a[0]), "r"(a[1]), "r"(a[2]), "r"(a[3]), "r"(b[0]), "r"(b[1]));
}

template <bool PBW, bool ADD_BIAS, bool WVEC>
__global__ __launch_bounds__(256) void mma_gemm_kernel(
    const float* __restrict__ W, const float* __restrict__ X,
    float* __restrict__ Y, const float* __restrict__ bias,
    float* __restrict__ stats, int O, int I, int Nn) {
    constexpr int BM = 64, BN = 128, BK = 16;
    __shared__ unsigned Ah[BK][BM + 4], Al[BK][BM + 4];
    __shared__ unsigned Bh[BK][BN + 4], Bl[BK][BN + 4];
    __shared__ float sred1[4][64], sred2[4][64];

    int b = blockIdx.z;
    const float* Wb = W + (PBW ? (size_t)b * O * I : 0);
    const float* Xb = X + (size_t)b * I * Nn;
    int o0 = blockIdx.y * BM, n0 = blockIdx.x * BN;
    int tid = threadIdx.x, lane = tid & 31, wid = tid >> 5;
    int wo = (wid >> 2) * 32, wn = (wid & 3) * 32;
    int g = lane >> 2, tg = lane & 3;
    int wnw = wid & 3;

    float acc[2][4][4];
#pragma unroll
    for (int mi = 0; mi < 2; mi++)
#pragma unroll
        for (int ni = 0; ni < 4; ni++)
#pragma unroll
            for (int q = 0; q < 4; q++) acc[mi][ni][q] = 0.f;

    int nsteps = (I + BK - 1) / BK;
    for (int s = 0; s < nsteps; s++) {
        int i0 = s * BK;
        if (WVEC) {
            // 64x16 = 1024 floats = 256 threads x 1 float4 (I % 16 == 0)
            int r = tid >> 2, c0 = (tid & 3) * 4;
            float4 wv = *(const float4*)(Wb + (size_t)(o0 + r) * I + i0 + c0);
            unsigned h;
            h = f2tf(wv.x); Ah[c0 + 0][r] = h; Al[c0 + 0][r] = f2tf(wv.x - __uint_as_float(h));
            h = f2tf(wv.y); Ah[c0 + 1][r] = h; Al[c0 + 1][r] = f2tf(wv.y - __uint_as_float(h));
            h = f2tf(wv.z); Ah[c0 + 2][r] = h; Al[c0 + 2][r] = f2tf(wv.z - __uint_as_float(h));
            h = f2tf(wv.w); Ah[c0 + 3][r] = h; Al[c0 + 3][r] = f2tf(wv.w - __uint_as_float(h));
        } else {
#pragma unroll
            for (int l = 0; l < 4; l++) {
                int idx = tid + l * 256;
                int r = idx >> 4, c = idx & 15;
                float v = (i0 + c < I) ? Wb[(size_t)(o0 + r) * I + i0 + c] : 0.f;
                unsigned h = f2tf(v);
                Ah[c][r] = h;
                Al[c][r] = f2tf(v - __uint_as_float(h));
            }
        }
#pragma unroll
        for (int l = 0; l < 2; l++) {
            // 16x128 = 2048 floats = 256 threads x 2 float4
            int f4 = tid + l * 256;
            int k = f4 >> 5, n4 = (f4 & 31) * 4;
            float4 xv = (i0 + k < I)
                ? *(const float4*)(Xb + (size_t)(i0 + k) * Nn + n0 + n4)
                : make_float4(0.f, 0.f, 0.f, 0.f);
            unsigned h;
            h = f2tf(xv.x); Bh[k][n4 + 0] = h; Bl[k][n4 + 0] = f2tf(xv.x - __uint_as_float(h));
            h = f2tf(xv.y); Bh[k][n4 + 1] = h; Bl[k][n4 + 1] = f2tf(xv.y - __uint_as_float(h));
            h = f2tf(xv.z); Bh[k][n4 + 2] = h; Bl[k][n4 + 2] = f2tf(xv.z - __uint_as_float(h));
            h = f2tf(xv.w); Bh[k][n4 + 3] = h; Bl[k][n4 + 3] = f2tf(xv.w - __uint_as_float(h));
        }
        __syncthreads();
#pragma unroll
        for (int kk = 0; kk < 2; kk++) {
            unsigned ah[2][4], al[2][4], bh[4][2], bl[4][2];
#pragma unroll
            for (int mi = 0; mi < 2; mi++) {
                int r0 = wo + mi * 16 + g;
                ah[mi][0] = Ah[kk * 8 + tg][r0];
                ah[mi][1] = Ah[kk * 8 + tg][r0 + 8];
                ah[mi][2] = Ah[kk * 8 + tg + 4][r0];
                ah[mi][3] = Ah[kk * 8 + tg + 4][r0 + 8];
                al[mi][0] = Al[kk * 8 + tg][r0];
                al[mi][1] = Al[kk * 8 + tg][r0 + 8];
                al[mi][2] = Al[kk * 8 + tg + 4][r0];
                al[mi][3] = Al[kk * 8 + tg + 4][r0 + 8];
            }
#pragma unroll
            for (int ni = 0; ni < 4; ni++) {
                int c0 = wn + ni * 8 + g;
                bh[ni][0] = Bh[kk * 8 + tg][c0];
                bh[ni][1] = Bh[kk * 8 + tg + 4][c0];
                bl[ni][0] = Bl[kk * 8 + tg][c0];
                bl[ni][1] = Bl[kk * 8 + tg + 4][c0];
            }
#pragma unroll
            for (int mi = 0; mi < 2; mi++)
#pragma unroll
                for (int ni = 0; ni < 4; ni++) {
                    mma8(acc[mi][ni], ah[mi], bh[ni]);
                    mma8(acc[mi][ni], ah[mi], bl[ni]);
                    mma8(acc[mi][ni], al[mi], bh[ni]);
                }
        }
        __syncthreads();
    }

    float* Yb = Y + (size_t)b * O * Nn;
    int mI = (n0 + wn) >> 5;   // constant across the warp tile (wn multiple of 32)
#pragma unroll
    for (int mi = 0; mi < 2; mi++) {
        int r1 = o0 + wo + mi * 16 + g, r2 = r1 + 8;
        float b1 = 0.f, b2 = 0.f;
        if (ADD_BIAS) {
            b1 = bias[((size_t)b * O + r1) * (size_t)(Nn >> 5) + mI];
            b2 = bias[((size_t)b * O + r2) * (size_t)(Nn >> 5) + mI];
        }
        float sA = 0.f, qA = 0.f, sB = 0.f, qB = 0.f;
#pragma unroll
        for (int ni = 0; ni < 4; ni++) {
            int c = n0 + wn + ni * 8 + 2 * tg;
            float v0 = acc[mi][ni][0] + b1, v1 = acc[mi][ni][1] + b1;
            float v2 = acc[mi][ni][2] + b2, v3 = acc[mi][ni][3] + b2;
            *(float2*)(Yb + (size_t)r1 * Nn + c) = make_float2(v0, v1);
            *(float2*)(Yb + (size_t)r2 * Nn + c) = make_float2(v2, v3);
            sA += v0 + v1; qA += v0 * v0 + v1 * v1;
            sB += v2 + v3; qB += v2 * v2 + v3 * v3;
        }
        // reduce across the 4 lanes sharing rows (tg group)
#pragma unroll
        for (int o = 1; o < 4; o <<= 1) {
            sA += __shfl_xor_sync(0xffffffffu, sA, o);
            qA += __shfl_xor_sync(0xffffffffu, qA, o);
            sB += __shfl_xor_sync(0xffffffffu, sB, o);
            qB += __shfl_xor_sync(0xffffffffu, qB, o);
        }
        if (tg == 0) {
            int lr1 = r1 - o0, lr2 = r2 - o0;
            sred1[wnw][lr1] = sA; sred2[wnw][lr1] = qA;
            sred1[wnw][lr2] = sB; sred2[wnw][lr2] = qB;
        }
    }
    __syncthreads();
    if (tid < 64) {
        float a = sred1[0][tid] + sred1[1][tid] + sred1[2][tid] + sred1[3][tid];
        atomicAdd(&stats[((size_t)b * O + o0 + tid) * 2], a);
    } else if (tid < 128) {
        int r = tid - 64;
        float q = sred2[0][r] + sred2[1][r] + sred2[2][r] + sred2[3][r];
        atomicAdd(&stats[((size_t)b * O + o0 + r) * 2 + 1], q);
    }
}

// ============================================================================
// FFMA SGEMM for the small bias GEMMs
// ============================================================================
template <bool PBW>
__global__ void gemm_kernel(const float* __restrict__ W,
                            const float* __restrict__ X,
                            float* __restrict__ Y,
                            int O, int I, int Nn) {
    constexpr int BO = 64, BN = 128, BK = 8;
    __shared__ float Ws[BK][BO];
    __shared__ float Xs[BK][BN];

    int b = blockIdx.z;
    const float* Wb = W + (PBW ? (size_t)b * O * I : 0);
    const float* Xb = X + (size_t)b * I * Nn;
    float* Yb = Y + (size_t)b * O * Nn;
    int o0 = blockIdx.y * BO, n0 = blockIdx.x * BN;
    int tid = threadIdx.x;
    int tx = tid & 15, ty = tid >> 4;

    float acc[4][8];
#pragma unroll
    for (int u = 0; u < 4; u++)
#pragma unroll
        for (int v = 0; v < 8; v++) acc[u][v] = 0.f;

    for (int i0 = 0; i0 < I; i0 += BK) {
#pragma unroll
        for (int l = 0; l < 2; l++) {
            int idx = tid + l * 256;
            int k = idx >> 6, o = idx & 63;
            int ii = i0 + k;
            Ws[k][o] = (ii < I) ? Wb[(size_t)(o0 + o) * I + ii] : 0.f;
        }
#pragma unroll
        for (int l = 0; l < 4; l++) {
            int idx = tid + l * 256;
            int k = idx >> 7, n = idx & 127;
            int ii = i0 + k;
            Xs[k][n] = (ii < I) ? Xb[(size_t)ii * Nn + n0 + n] : 0.f;
        }
        __syncthreads();
#pragma unroll
        for (int kk = 0; kk < BK; kk++) {
            float a[4], x[8];
#pragma unroll
            for (int u = 0; u < 4; u++) a[u] = Ws[kk][ty * 4 + u];
#pragma unroll
            for (int v = 0; v < 8; v++) x[v] = Xs[kk][tx * 8 + v];
#pragma unroll
            for (int u = 0; u < 4; u++)
#pragma unroll
                for (int v = 0; v < 8; v++) acc[u][v] += a[u] * x[v];
        }
        __syncthreads();
    }
#pragma unroll
    for (int u = 0; u < 4; u++) {
        int o = o0 + ty * 4 + u;
        float* yr = Yb + (size_t)o * Nn + n0 + tx * 8;
#pragma unroll
        for (int v = 0; v < 8; v++) yr[v] = acc[u][v];
    }
}

// ============================================================================
// Vectorized stats (float4) — used only for conv1-s0 output. Zeroes xsum.
// ============================================================================
__global__ void stats_kernel(const float* __restrict__ Y,
                             float* __restrict__ stats,
                             float* __restrict__ xsum, int NMK) {
    __shared__ float sh1[32], sh2[32];
    int bo = blockIdx.x;
    const float4* y4 = (const float4*)(Y + (size_t)bo * NMK);
    int n4 = NMK >> 2;
    float s = 0.f, s2 = 0.f;
#pragma unroll 4
    for (int i = threadIdx.x; i < n4; i += blockDim.x) {
        float4 v = y4[i];
        s  += (v.x + v.y) + (v.z + v.w);
        s2 += (v.x * v.x + v.y * v.y) + (v.z * v.z + v.w * v.w);
    }
#pragma unroll
    for (int o = 16; o; o >>= 1) {
        s  += __shfl_down_sync(0xffffffffu, s, o);
        s2 += __shfl_down_sync(0xffffffffu, s2, o);
    }
    int w = threadIdx.x >> 5, l = threadIdx.x & 31;
    if (l == 0) { sh1[w] = s; sh2[w] = s2; }
    __syncthreads();
    if (threadIdx.x == 0) {
        float a = 0.f, c = 0.f;
        int nw = blockDim.x >> 5;
        for (int i = 0; i < nw; i++) { a += sh1[i]; c += sh2[i]; }
        stats[bo * 2] = a; stats[bo * 2 + 1] = c;
        xsum[bo] = 0.f;
    }
}

// clear stats + xsum before mma launches
__global__ void clear_kernel(float* __restrict__ stats, float* __restrict__ xsum) {
    int i = blockIdx.x * blockDim.x + threadIdx.x;
    if (i < B_ * 384 * 2) stats[i] = 0.f;
    if (i < B_ * 384)     xsum[i]  = 0.f;
}

// ============================================================================
// normalize v2 (float4): x=relu((y-mean)*rs); opt write; per-(b,o,m) max;
// per-(b,o) sum. Block = 256 threads = 64 m-rows (4 threads x 8 elems per m).
// ============================================================================
template <bool WRITE>
__global__ void normalize_kernel(float* __restrict__ Y,
                                 const float* __restrict__ stats,
                                 float* __restrict__ rawmax,
                                 float* __restrict__ xsum,
                                 int M, float invNMK) {
    __shared__ float swarp[8];
    int chunks = M >> 6;
    int bo = blockIdx.x / chunks;
    int m0 = (blockIdx.x % chunks) * 64;
    int warp = threadIdx.x >> 5, lane = threadIdx.x & 31;
    int m = m0 + warp * 8 + (lane >> 2);
    float mean = stats[bo * 2] * invNMK;
    float var  = stats[bo * 2 + 1] * invNMK - mean * mean;
    float rs = rsqrtf(var + 1e-5f);
    size_t base = (((size_t)bo * M + m) << 5) + ((size_t)(lane & 3) << 3);
    float4 a = *(float4*)(Y + base);
    float4 c = *(float4*)(Y + base + 4);
    a.x = fmaxf((a.x - mean) * rs, 0.f); a.y = fmaxf((a.y - mean) * rs, 0.f);
    a.z = fmaxf((a.z - mean) * rs, 0.f); a.w = fmaxf((a.w - mean) * rs, 0.f);
    c.x = fmaxf((c.x - mean) * rs, 0.f); c.y = fmaxf((c.y - mean) * rs, 0.f);
    c.z = fmaxf((c.z - mean) * rs, 0.f); c.w = fmaxf((c.w - mean) * rs, 0.f);
    if (WRITE) {
        *(float4*)(Y + base)     = a;
        *(float4*)(Y + base + 4) = c;
    }
    float mx = fmaxf(fmaxf(fmaxf(a.x, a.y), fmaxf(a.z, a.w)),
                     fmaxf(fmaxf(c.x, c.y), fmaxf(c.z, c.w)));
    float sm = ((a.x + a.y) + (a.z + a.w)) + ((c.x + c.y) + (c.z + c.w));
    // max over 4 lanes of same m
    mx = fmaxf(mx, __shfl_xor_sync(0xffffffffu, mx, 1));
    mx = fmaxf(mx, __shfl_xor_sync(0xffffffffu, mx, 2));
    if ((lane & 3) == 0) rawmax[(size_t)bo * M + m] = mx;
    // warp total sum (8 m-rows) then block reduce
#pragma unroll
    for (int o = 16; o; o >>= 1) sm += __shfl_down_sync(0xffffffffu, sm, o);
    if (lane == 0) swarp[warp] = sm;
    __syncthreads();
    if (threadIdx.x == 0) {
        float tt = 0.f;
        for (int w = 0; w < 8; w++) tt += swarp[w];
        atomicAdd(&xsum[bo], tt);
    }
}

// ============================================================================
// Channel attention gate
// ============================================================================
__global__ void gate_kernel(const float* __restrict__ xsum,
                            const float* __restrict__ w1,
                            const float* __restrict__ w2,
                            float* __restrict__ gate,
                            int O, int H, float invNMK) {
    __shared__ float s[384];
    __shared__ float h[96];
    int b = blockIdx.x, t = threadIdx.x;
    s[t] = xsum[b * O + t] * invNMK;
    __syncthreads();
    if (t < H) {
        float a = 0.f;
        for (int o = 0; o < O; o++) a += s[o] * w1[t * O + o];
        h[t] = fmaxf(a, 0.f);
    }
    __syncthreads();
    float a = 0.f;
    for (int j = 0; j < H; j++) a += h[j] * w2[t * H + j];
    gate[b * O + t] = 1.f / (1.f + expf(-a));
}

__global__ void scale_w_kernel(const float* __restrict__ W,
                               const float* __restrict__ gate,
                               float* __restrict__ Wa, float* __restrict__ Wb,
                               int O, int C) {
    int idx = blockIdx.x * blockDim.x + threadIdx.x;
    int total = B_ * O * C;
    if (idx >= total) return;
    int b = idx / (O * C);
    int r = idx % (O * C);
    int o = r / C, i = r % C;
    float g = gate[b * C + i];
    Wa[idx] = W[(size_t)o * (2 * C) + i] * g;
    Wb[idx] = W[(size_t)o * (2 * C) + C + i] * g;
}

__global__ void fout_kernel(const float* __restrict__ gate,
                            const float* __restrict__ rawmax,
                            float* __restrict__ f1, float* __restrict__ out,
                            int M, int total) {
    int i = blockIdx.x * blockDim.x + threadIdx.x;
    if (i >= total) return;
    int bo = i / M;
    float v = gate[bo] * rawmax[i];
    if (f1) f1[i] = v;
    out[i] = v;
}

// ============================================================================
// Host
// ============================================================================
extern "C" void kernel_launch(void* const* d_in, const int* in_sizes, int n_in,
                              void* d_out, int out_size) {
    const float* p      = (const float*)d_in[0];
    const float* f      = (const float*)d_in[1];
    const float* s0_w1  = (const float*)d_in[2];
    const float* s0_a1w1= (const float*)d_in[3];
    const float* s0_a1w2= (const float*)d_in[4];
    const float* s0_w2  = (const float*)d_in[5];
    const float* s0_a2w1= (const float*)d_in[6];
    const float* s0_a2w2= (const float*)d_in[7];
    const float* s1_w1  = (const float*)d_in[8];
    const float* s1_a1w1= (const float*)d_in[9];
    const float* s1_a1w2= (const float*)d_in[10];
    const float* s1_w2  = (const float*)d_in[11];
    const float* s1_a2w1= (const float*)d_in[12];
    const float* s1_a2w2= (const float*)d_in[13];
    float* out = (float*)d_out;

    float *feat, *Y, *Y2, *cp1, *cp2, *stats, *xsum, *rm1, *rm2, *gate, *Wa, *Wb, *bias, *f1;
    int *idx1, *idx2, *gidx;
    cudaGetSymbolAddress((void**)&feat, g_feat);
    cudaGetSymbolAddress((void**)&Y,    g_Y);
    cudaGetSymbolAddress((void**)&Y2,   g_Y2);
    cudaGetSymbolAddress((void**)&idx1, g_idx1);
    cudaGetSymbolAddress((void**)&idx2, g_idx2);
    cudaGetSymbolAddress((void**)&gidx, g_gidx);
    cudaGetSymbolAddress((void**)&cp1,  g_cp1);
    cudaGetSymbolAddress((void**)&cp2,  g_cp2);
    cudaGetSymbolAddress((void**)&stats,g_stats);
    cudaGetSymbolAddress((void**)&xsum, g_xsum);
    cudaGetSymbolAddress((void**)&rm1,  g_rmax1);
    cudaGetSymbolAddress((void**)&rm2,  g_rmax2);
    cudaGetSymbolAddress((void**)&gate, g_gate);
    cudaGetSymbolAddress((void**)&Wa,   g_Wa);
    cudaGetSymbolAddress((void**)&Wb,   g_Wb);
    cudaGetSymbolAddress((void**)&bias, g_bias);
    cudaGetSymbolAddress((void**)&f1,   g_f1);

    cudaFuncSetAttribute(fps_kernel<8192, 2048, 1024>,
                         cudaFuncAttributeMaxDynamicSharedMemorySize, 8192 * 3 * 4);
    cudaFuncSetAttribute(fps_kernel<2048, 512, 256>,
                         cudaFuncAttributeMaxDynamicSharedMemorySize, 2048 * 3 * 4);

    const int N0 = 8192, M1 = 2048, M2 = 512;
    const int NMK0 = M1 * 32;
    const int NMK1 = M2 * 32;
    const float inv0 = 1.f / (float)NMK0;
    const float inv1 = 1.f / (float)NMK1;

    // -------------------- Stage 0 --------------------
    fps_kernel<8192, 2048, 1024><<<4, 1024, 8192 * 3 * 4>>>(p, idx1, cp1);
    ballquery_kernel<<<(B_ * M1) / 8, 256>>>(cp1, p, gidx, N0, M1);
    conv1s0_kernel<<<dim3(NMK0 / 256, B_), 256>>>(p, cp1, f, gidx, idx1, s0_w1, Y);
    stats_kernel<<<B_ * 192, 256>>>(Y, stats, xsum, NMK0);
    normalize_kernel<true><<<B_ * 192 * (M1 / 64), 256>>>(Y, stats, rm1, xsum, M1, inv0);
    gate_kernel<<<B_, 192>>>(xsum, s0_a1w1, s0_a1w2, gate, 192, 48, inv0);
    scale_w_kernel<<<(B_ * 192 * 192 + 255) / 256, 256>>>(s0_w2, gate, Wa, Wb, 192, 192);

    gemm_kernel<true><<<dim3(M1 / 128, 192 / 64, B_), 256>>>(Wa, rm1, bias, 192, 192, M1);
    clear_kernel<<<12, 256>>>(stats, xsum);
    mma_gemm_kernel<true, true, true><<<dim3(NMK0 / 128, 192 / 64, B_), 256>>>(
        Wb, Y, Y2, bias, stats, 192, 192, NMK0);
    normalize_kernel<false><<<B_ * 192 * (M1 / 64), 256>>>(Y2, stats, rm2, xsum, M1, inv0);
    gate_kernel<<<B_, 192>>>(xsum, s0_a2w1, s0_a2w2, gate, 192, 48, inv0);
    fout_kernel<<<(B_ * 192 * M1 + 255) / 256, 256>>>(
        gate, rm2, f1, out + 227328, M1, B_ * 192 * M1);

    // -------------------- Stage 1 --------------------
    fps_kernel<2048, 512, 256><<<4, 256, 2048 * 3 * 4>>>(cp1, idx2, cp2);
    ballquery_kernel<<<(B_ * M2) / 8, 256>>>(cp2, cp1, gidx, M1, M2);
    build_feat_kernel<<<dim3(M2, B_), 128>>>(cp1, cp2, f1, gidx, idx2, feat, M1, M2, 192);

    clear_kernel<<<12, 256>>>(stats, xsum);
    mma_gemm_kernel<false, false, false><<<dim3(NMK1 / 128, 384 / 64, B_), 256>>>(
        s1_w1, feat, Y, nullptr, stats, 384, 195, NMK1);
    normalize_kernel<true><<<B_ * 384 * (M2 / 64), 256>>>(Y, stats, rm1, xsum, M2, inv1);
    gate_kernel<<<B_, 384>>>(xsum, s1_a1w1, s1_a1w2, gate, 384, 96, inv1);
    scale_w_kernel<<<(B_ * 384 * 384 + 255) / 256, 256>>>(s1_w2, gate, Wa, Wb, 384, 384);

    gemm_kernel<true><<<dim3(M2 / 128, 384 / 64, B_), 256>>>(Wa, rm1, bias, 384, 384, M2);
    clear_kernel<<<12, 256>>>(stats, xsum);
    mma_gemm_kernel<true, true, true><<<dim3(NMK1 / 128, 384 / 64, B_), 256>>>(
        Wb, Y, Y2, bias, stats, 384, 384, NMK1);
    normalize_kernel<false><<<B_ * 384 * (M2 / 64), 256>>>(Y2, stats, rm2, xsum, M2, inv1);
    gate_kernel<<<B_, 384>>>(xsum, s1_a2w1, s1_a2w2, gate, 384, 96, inv1);
    fout_kernel<<<(B_ * 384 * M2 + 255) / 256, 256>>>(
        gate, rm2, nullptr, out + 1800192, M2, B_ * 384 * M2);

    // -------------------- passthrough outputs --------------------
    cudaMemcpyAsync(out + 0,      p,   (size_t)98304 * 4, cudaMemcpyDeviceToDevice);
    cudaMemcpyAsync(out + 98304,  cp1, (size_t)24576 * 4, cudaMemcpyDeviceToDevice);
    cudaMemcpyAsync(out + 122880, cp2, (size_t)6144 * 4,  cudaMemcpyDeviceToDevice);
    cudaMemcpyAsync(out + 129024, f,   (size_t)98304 * 4, cudaMemcpyDeviceToDevice);
}

// round 5
// speedup vs baseline: 1.7171x; 1.7171x over previous
#include <cuda_runtime.h>
#include <cstdint>
#include <cstddef>

#define B_ 4
#define KNB 32

// ---------------- device scratch (no cudaMalloc allowed) ----------------
__device__ float g_feat[(size_t)4 * 195 * 16384];
__device__ float g_Y [(size_t)4 * 192 * 65536];
__device__ float g_Y2[(size_t)4 * 192 * 65536];
__device__ int   g_idx1[4 * 2048];
__device__ int   g_idx2[4 * 512];
__device__ int   g_gidx[4 * 2048 * 32];
__device__ float g_cp1[4 * 2048 * 3];
__device__ float g_cp2[4 * 512 * 3];
__device__ float g_stats[4 * 384 * 2];
__device__ float g_xsum[4 * 384];
__device__ float g_rmax1[(size_t)4 * 192 * 2048];
__device__ float g_rmax2[(size_t)4 * 192 * 2048];
__device__ float g_gate[4 * 384];
__device__ float g_Wa[4 * 384 * 384];
__device__ float g_Wb[4 * 384 * 384];
__device__ float g_bias[(size_t)4 * 192 * 2048];
__device__ float g_f1[(size_t)4 * 192 * 2048];

// ---------------- packed f32x2 helpers (exact per-half rn) ----------------
__device__ __forceinline__ unsigned long long packf2(float lo, float hi) {
    unsigned long long r;
    asm("mov.b64 %0, {%1, %2};" : "=l"(r) : "f"(lo), "f"(hi));
    return r;
}
__device__ __forceinline__ void unpackf2(unsigned long long v, float& lo, float& hi) {
    asm("mov.b64 {%0, %1}, %2;" : "=f"(lo), "=f"(hi) : "l"(v));
}
__device__ __forceinline__ unsigned long long addx2(unsigned long long a, unsigned long long b) {
    unsigned long long r;
    asm("add.rn.f32x2 %0, %1, %2;" : "=l"(r) : "l"(a), "l"(b));
    return r;
}
__device__ __forceinline__ unsigned long long mulx2(unsigned long long a, unsigned long long b) {
    unsigned long long r;
    asm("mul.rn.f32x2 %0, %1, %2;" : "=l"(r) : "l"(a), "l"(b));
    return r;
}

// ============================================================================
// FPS v3 (R3-exact) — packed distance math, REDUX argmax, 1 barrier/iter.
// ============================================================================
template <int N, int M, int T>
__global__ void fps_kernel(const float* __restrict__ p,
                           int* __restrict__ idx_out,
                           float* __restrict__ cp_out) {
    extern __shared__ float sm[];
    float* sx = sm;
    float* sy = sm + N;
    float* sz = sm + 2 * N;
    constexpr int PPT = N / T;
    constexpr int NP  = PPT / 2;
    constexpr int NW  = T / 32;
    __shared__ unsigned sval[2][NW];
    __shared__ int      sidx[2][NW];

    const int b = blockIdx.x;
    const int t = threadIdx.x;
    const int lane = t & 31, w = t >> 5;
    const float* pb = p + (size_t)b * N * 3;

    for (int i = t; i < N; i += T) {
        sx[i] = pb[i * 3 + 0];
        sy[i] = pb[i * 3 + 1];
        sz[i] = pb[i * 3 + 2];
    }
    __syncthreads();

    unsigned long long pxp[NP], pyp[NP], pzp[NP];
    float dist[PPT];
#pragma unroll
    for (int i = 0; i < NP; i++) {
        int g0 = t * PPT + 2 * i;
        pxp[i] = packf2(sx[g0], sx[g0 + 1]);
        pyp[i] = packf2(sy[g0], sy[g0 + 1]);
        pzp[i] = packf2(sz[g0], sz[g0 + 1]);
        dist[2 * i] = 1e10f; dist[2 * i + 1] = 1e10f;
    }

    float lx = sx[0], ly = sy[0], lz = sz[0];
    if (t == 0) {
        idx_out[b * M] = 0;
        cp_out[(size_t)b * M * 3 + 0] = lx;
        cp_out[(size_t)b * M * 3 + 1] = ly;
        cp_out[(size_t)b * M * 3 + 2] = lz;
    }

    for (int j = 1; j < M; j++) {
        unsigned long long nx = packf2(-lx, -lx);
        unsigned long long ny = packf2(-ly, -ly);
        unsigned long long nz = packf2(-lz, -lz);
        float bv = -1.0f; int bi = 0;
#pragma unroll
        for (int i = 0; i < NP; i++) {
            unsigned long long dx = addx2(pxp[i], nx);
            unsigned long long dy = addx2(pyp[i], ny);
            unsigned long long dz = addx2(pzp[i], nz);
            unsigned long long s  = addx2(addx2(mulx2(dx, dx), mulx2(dy, dy)), mulx2(dz, dz));
            float d0, d1; unpackf2(s, d0, d1);
            float m0 = fminf(dist[2 * i], d0);     dist[2 * i] = m0;
            if (m0 > bv) { bv = m0; bi = t * PPT + 2 * i; }
            float m1 = fminf(dist[2 * i + 1], d1); dist[2 * i + 1] = m1;
            if (m1 > bv) { bv = m1; bi = t * PPT + 2 * i + 1; }
        }
        unsigned vb = __float_as_uint(bv);
        unsigned wm = __reduce_max_sync(0xffffffffu, vb);
        int cand = (vb == wm) ? bi : 0x7fffffff;
        int wi   = __reduce_min_sync(0xffffffffu, cand);
        int par = j & 1;
        if (lane == 0) { sval[par][w] = wm; sidx[par][w] = wi; }
        __syncthreads();
        unsigned v2 = (lane < NW) ? sval[par][lane] : 0u;
        unsigned m2 = __reduce_max_sync(0xffffffffu, v2);
        int c2 = (lane < NW && v2 == m2) ? sidx[par][lane] : 0x7fffffff;
        int ii = __reduce_min_sync(0xffffffffu, c2);
        lx = sx[ii]; ly = sy[ii]; lz = sz[ii];
        if (t == 0) {
            idx_out[b * M + j] = ii;
            cp_out[((size_t)b * M + j) * 3 + 0] = lx;
            cp_out[((size_t)b * M + j) * 3 + 1] = ly;
            cp_out[((size_t)b * M + j) * 3 + 2] = lz;
        }
    }
}

// ============================================================================
// Ball query (exact fp32 rn threshold math)
// ============================================================================
__global__ void ballquery_kernel(const float* __restrict__ cp,
                                 const float* __restrict__ p,
                                 int* __restrict__ gidx, int N, int M) {
    int wid  = (blockIdx.x * blockDim.x + threadIdx.x) >> 5;
    int lane = threadIdx.x & 31;
    if (wid >= B_ * M) return;
    int b = wid / M, m = wid % M;

    const float* c = cp + ((size_t)b * M + m) * 3;
    float cx = c[0], cy = c[1], cz = c[2];
    const float* pb = p + (size_t)b * N * 3;
    int* row = gidx + ((size_t)b * M + m) * KNB;

    int cnt = 0;
    int firstIdx = -1;
    for (int base = 0; base < N && cnt < KNB; base += 32) {
        int i = base + lane;
        float dx = pb[i * 3 + 0] - cx;
        float dy = pb[i * 3 + 1] - cy;
        float dz = pb[i * 3 + 2] - cz;
        float d2 = __fadd_rn(__fadd_rn(__fmul_rn(dx, dx), __fmul_rn(dy, dy)),
                             __fmul_rn(dz, dz));
        bool within = d2 < 0.01f;
        unsigned ball = __ballot_sync(0xffffffffu, within);
        if (within) {
            int pos = cnt + __popc(ball & ((1u << lane) - 1u));
            if (pos < KNB) row[pos] = i;
        }
        if (firstIdx < 0 && ball) firstIdx = base + (__ffs(ball) - 1);
        cnt += __popc(ball);
    }
    if (cnt > KNB) cnt = KNB;
    if (firstIdx < 0) firstIdx = 0;
    for (int pos = cnt + lane; pos < KNB; pos += 32) row[pos] = firstIdx;
}

// ============================================================================
// Stage0 conv1 fused: gather + (p-cp, f-cf) + 192x6 direct conv.
// ============================================================================
__global__ void conv1s0_kernel(const float* __restrict__ p,
                               const float* __restrict__ cp,
                               const float* __restrict__ f,
                               const int* __restrict__ gidx,
                               const int* __restrict__ cidx,
                               const float* __restrict__ W,
                               float* __restrict__ Y) {
    __shared__ float ws[192 * 6];
    int b = blockIdx.y;
    int tid = threadIdx.x;
    for (int i = tid; i < 192 * 6; i += 256) ws[i] = W[i];
    int mk = blockIdx.x * 256 + tid;
    int m = mk >> 5;
    int g = gidx[((size_t)b * 2048 + m) * 32 + (mk & 31)];
    int ci = cidx[b * 2048 + m];
    __syncthreads();

    float v[6];
    const float* pg = p + ((size_t)b * 8192 + g) * 3;
    const float* cm = cp + ((size_t)b * 2048 + m) * 3;
    v[0] = pg[0] - cm[0]; v[1] = pg[1] - cm[1]; v[2] = pg[2] - cm[2];
    const float* fb = f + (size_t)b * 3 * 8192;
    v[3] = fb[g] - fb[ci];
    v[4] = fb[8192 + g] - fb[8192 + ci];
    v[5] = fb[16384 + g] - fb[16384 + ci];

    float* yb = Y + (size_t)b * 192 * 65536 + mk;
#pragma unroll 4
    for (int o = 0; o < 192; o++) {
        const float* wr = ws + o * 6;
        float a = wr[0] * v[0] + wr[1] * v[1] + wr[2] * v[2]
                + wr[3] * v[3] + wr[4] * v[4] + wr[5] * v[5];
        yb[(size_t)o * 65536] = a;
    }
}

// ============================================================================
// Build feat for stage1 (C=192)
// ============================================================================
__global__ void build_feat_kernel(const float* __restrict__ p,
                                  const float* __restrict__ cp,
                                  const float* __restrict__ f,
                                  const int* __restrict__ gidx,
                                  const int* __restrict__ cidx,
                                  float* __restrict__ feat,
                                  int N, int M, int C) {
    __shared__ int sg[KNB];
    int b = blockIdx.y, m = blockIdx.x, tid = threadIdx.x;
    if (tid < KNB) sg[tid] = gidx[((size_t)b * M + m) * KNB + tid];
    __syncthreads();
    int ci = cidx[b * M + m];
    size_t MK = (size_t)M * KNB;
    size_t fbase = (size_t)b * (3 + C) * MK + (size_t)m * KNB;

    if (tid < 3 * KNB) {
        int c = tid / KNB, k = tid % KNB;
        int g = sg[k];
        feat[fbase + (size_t)c * MK + k] =
            p[((size_t)b * N + g) * 3 + c] - cp[((size_t)b * M + m) * 3 + c];
    }
    for (int t = tid; t < C * KNB; t += blockDim.x) {
        int c = t / KNB, k = t % KNB;
        int g = sg[k];
        const float* frow = f + ((size_t)b * C + c) * N;
        feat[fbase + (size_t)(3 + c) * MK + k] = frow[g] - frow[ci];
    }
}

// ============================================================================
// TF32 tensor-core GEMM with 3-term split (R3-exact; fp32-grade accuracy).
// ============================================================================
__device__ __forceinline__ unsigned f2tf(float x) {
    unsigned r; asm("cvt.rna.tf32.f32 %0, %1;" : "=r"(r) : "f"(x)); return r;
}
__device__ __forceinline__ void mma8(float* d, const unsigned* a, const unsigned* b) {
    asm volatile("mma.sync.aligned.m16n8k8.row.col.f32.tf32.tf32.f32 "
                 "{%0,%1,%2,%3}, {%4,%5,%6,%7}, {%8,%9}, {%0,%1,%2,%3};"
                 : "+f"(d[0]), "+f"(d[1]), "+f"(d[2]), "+f"(d[3])
                 : "r"(a[0]), "r"(a[1]), "r"(a[2]), "r"(a[3]), "r"(b[0]), "r"(b[1]));
}

template <bool PBW, bool ADD_BIAS>
__global__ __launch_bounds__(256) void mma_gemm_kernel(
    const float* __restrict__ W, const float* __restrict__ X,
    float* __restrict__ Y, const float* __restrict__ bias,
    int O, int I, int Nn) {
    constexpr int BM = 64, BN = 128, BK = 16;
    __shared__ unsigned Ah[BK][BM + 4], Al[BK][BM + 4];
    __shared__ unsigned Bh[BK][BN + 4], Bl[BK][BN + 4];

    int b = blockIdx.z;
    const float* Wb = W + (PBW ? (size_t)b * O * I : 0);
    const float* Xb = X + (size_t)b * I * Nn;
    int o0 = blockIdx.y * BM, n0 = blockIdx.x * BN;
    int tid = threadIdx.x, lane = tid & 31, wid = tid >> 5;
    int wo = (wid >> 2) * 32, wn = (wid & 3) * 32;
    int g = lane >> 2, tg = lane & 3;

    float acc[2][4][4];
#pragma unroll
    for (int mi = 0; mi < 2; mi++)
#pragma unroll
        for (int ni = 0; ni < 4; ni++)
#pragma unroll
            for (int q = 0; q < 4; q++) acc[mi][ni][q] = 0.f;

    int nsteps = (I + BK - 1) / BK;
    for (int s = 0; s < nsteps; s++) {
        int i0 = s * BK;
#pragma unroll
        for (int l = 0; l < 4; l++) {
            int idx = tid + l * 256;
            int r = idx >> 4, c = idx & 15;
            float v = (i0 + c < I) ? Wb[(size_t)(o0 + r) * I + i0 + c] : 0.f;
            unsigned h = f2tf(v);
            Ah[c][r] = h;
            Al[c][r] = f2tf(v - __uint_as_float(h));
        }
#pragma unroll
        for (int l = 0; l < 8; l++) {
            int idx = tid + l * 256;
            int k = idx >> 7, n = idx & 127;
            float v = (i0 + k < I) ? Xb[(size_t)(i0 + k) * Nn + n0 + n] : 0.f;
            unsigned h = f2tf(v);
            Bh[k][n] = h;
            Bl[k][n] = f2tf(v - __uint_as_float(h));
        }
        __syncthreads();
#pragma unroll
        for (int kk = 0; kk < 2; kk++) {
            unsigned ah[2][4], al[2][4], bh[4][2], bl[4][2];
#pragma unroll
            for (int mi = 0; mi < 2; mi++) {
                int r0 = wo + mi * 16 + g;
                ah[mi][0] = Ah[kk * 8 + tg][r0];
                ah[mi][1] = Ah[kk * 8 + tg][r0 + 8];
                ah[mi][2] = Ah[kk * 8 + tg + 4][r0];
                ah[mi][3] = Ah[kk * 8 + tg + 4][r0 + 8];
                al[mi][0] = Al[kk * 8 + tg][r0];
                al[mi][1] = Al[kk * 8 + tg][r0 + 8];
                al[mi][2] = Al[kk * 8 + tg + 4][r0];
                al[mi][3] = Al[kk * 8 + tg + 4][r0 + 8];
            }
#pragma unroll
            for (int ni = 0; ni < 4; ni++) {
                int c0 = wn + ni * 8 + g;
                bh[ni][0] = Bh[kk * 8 + tg][c0];
                bh[ni][1] = Bh[kk * 8 + tg + 4][c0];
                bl[ni][0] = Bl[kk * 8 + tg][c0];
                bl[ni][1] = Bl[kk * 8 + tg + 4][c0];
            }
#pragma unroll
            for (int mi = 0; mi < 2; mi++)
#pragma unroll
                for (int ni = 0; ni < 4; ni++) {
                    mma8(acc[mi][ni], ah[mi], bh[ni]);
                    mma8(acc[mi][ni], ah[mi], bl[ni]);
                    mma8(acc[mi][ni], al[mi], bh[ni]);
                }
        }
        __syncthreads();
    }

    float* Yb = Y + (size_t)b * O * Nn;
#pragma unroll
    for (int mi = 0; mi < 2; mi++) {
        int r1 = o0 + wo + mi * 16 + g, r2 = r1 + 8;
#pragma unroll
        for (int ni = 0; ni < 4; ni++) {
            int c = n0 + wn + ni * 8 + 2 * tg;
            float b1 = 0.f, b2 = 0.f;
            if (ADD_BIAS) {
                int mI = c >> 5;
                b1 = bias[((size_t)b * O + r1) * (size_t)(Nn >> 5) + mI];
                b2 = bias[((size_t)b * O + r2) * (size_t)(Nn >> 5) + mI];
            }
            float2 v1 = make_float2(acc[mi][ni][0] + b1, acc[mi][ni][1] + b1);
            float2 v2 = make_float2(acc[mi][ni][2] + b2, acc[mi][ni][3] + b2);
            *(float2*)(Yb + (size_t)r1 * Nn + c) = v1;
            *(float2*)(Yb + (size_t)r2 * Nn + c) = v2;
        }
    }
}

// ============================================================================
// FFMA SGEMM for the small bias GEMMs (R3-exact)
// ============================================================================
template <bool PBW, bool ADD_BIAS>
__global__ void gemm_kernel(const float* __restrict__ W,
                            const float* __restrict__ X,
                            float* __restrict__ Y,
                            const float* __restrict__ bias,
                            int O, int I, int Nn) {
    constexpr int BO = 64, BN = 128, BK = 8;
    __shared__ float Ws[BK][BO];
    __shared__ float Xs[BK][BN];

    int b = blockIdx.z;
    const float* Wb = W + (PBW ? (size_t)b * O * I : 0);
    const float* Xb = X + (size_t)b * I * Nn;
    float* Yb = Y + (size_t)b * O * Nn;
    int o0 = blockIdx.y * BO, n0 = blockIdx.x * BN;
    int tid = threadIdx.x;
    int tx = tid & 15, ty = tid >> 4;

    float acc[4][8];
#pragma unroll
    for (int u = 0; u < 4; u++)
#pragma unroll
        for (int v = 0; v < 8; v++) acc[u][v] = 0.f;

    for (int i0 = 0; i0 < I; i0 += BK) {
#pragma unroll
        for (int l = 0; l < 2; l++) {
            int idx = tid + l * 256;
            int k = idx >> 6, o = idx & 63;
            int ii = i0 + k;
            Ws[k][o] = (ii < I) ? Wb[(size_t)(o0 + o) * I + ii] : 0.f;
        }
#pragma unroll
        for (int l = 0; l < 4; l++) {
            int idx = tid + l * 256;
            int k = idx >> 7, n = idx & 127;
            int ii = i0 + k;
            Xs[k][n] = (ii < I) ? Xb[(size_t)ii * Nn + n0 + n] : 0.f;
        }
        __syncthreads();
#pragma unroll
        for (int kk = 0; kk < BK; kk++) {
            float a[4], x[8];
#pragma unroll
            for (int u = 0; u < 4; u++) a[u] = Ws[kk][ty * 4 + u];
#pragma unroll
            for (int v = 0; v < 8; v++) x[v] = Xs[kk][tx * 8 + v];
#pragma unroll
            for (int u = 0; u < 4; u++)
#pragma unroll
                for (int v = 0; v < 8; v++) acc[u][v] += a[u] * x[v];
        }
        __syncthreads();
    }
#pragma unroll
    for (int u = 0; u < 4; u++) {
        int o = o0 + ty * 4 + u;
        float bv = 0.f;
        if (ADD_BIAS) bv = bias[((size_t)b * O + o) * (Nn >> 5) + ((n0 + tx * 8) >> 5)];
        float* yr = Yb + (size_t)o * Nn + n0 + tx * 8;
#pragma unroll
        for (int v = 0; v < 8; v++) yr[v] = acc[u][v] + bv;
    }
}

// ============================================================================
// Vectorized stats (float4): per-(b,o) sum/sumsq; zeroes xsum. (verified 3.3x)
// ============================================================================
__global__ void stats_kernel(const float* __restrict__ Y,
                             float* __restrict__ stats,
                             float* __restrict__ xsum, int NMK) {
    __shared__ float sh1[32], sh2[32];
    int bo = blockIdx.x;
    const float4* y4 = (const float4*)(Y + (size_t)bo * NMK);
    int n4 = NMK >> 2;
    float s = 0.f, s2 = 0.f;
#pragma unroll 4
    for (int i = threadIdx.x; i < n4; i += blockDim.x) {
        float4 v = y4[i];
        s  += (v.x + v.y) + (v.z + v.w);
        s2 += (v.x * v.x + v.y * v.y) + (v.z * v.z + v.w * v.w);
    }
#pragma unroll
    for (int o = 16; o; o >>= 1) {
        s  += __shfl_down_sync(0xffffffffu, s, o);
        s2 += __shfl_down_sync(0xffffffffu, s2, o);
    }
    int w = threadIdx.x >> 5, l = threadIdx.x & 31;
    if (l == 0) { sh1[w] = s; sh2[w] = s2; }
    __syncthreads();
    if (threadIdx.x == 0) {
        float a = 0.f, c = 0.f;
        int nw = blockDim.x >> 5;
        for (int i = 0; i < nw; i++) { a += sh1[i]; c += sh2[i]; }
        stats[bo * 2] = a; stats[bo * 2 + 1] = c;
        xsum[bo] = 0.f;
    }
}

// ============================================================================
// normalize v2 (float4): x=relu((y-mean)*rs); opt write; per-(b,o,m) max;
// per-(b,o) sum. 256 threads = 64 m-rows (4 threads x 8 elems per m).
// ============================================================================
template <bool WRITE>
__global__ void normalize_kernel(float* __restrict__ Y,
                                 const float* __restrict__ stats,
                                 float* __restrict__ rawmax,
                                 float* __restrict__ xsum,
                                 int M, float invNMK) {
    __shared__ float swarp[8];
    int chunks = M >> 6;
    int bo = blockIdx.x / chunks;
    int m0 = (blockIdx.x % chunks) * 64;
    int warp = threadIdx.x >> 5, lane = threadIdx.x & 31;
    int m = m0 + warp * 8 + (lane >> 2);
    float mean = stats[bo * 2] * invNMK;
    float var  = stats[bo * 2 + 1] * invNMK - mean * mean;
    float rs = rsqrtf(var + 1e-5f);
    size_t base = (((size_t)bo * M + m) << 5) + ((size_t)(lane & 3) << 3);
    float4 a = *(float4*)(Y + base);
    float4 c = *(float4*)(Y + base + 4);
    a.x = fmaxf((a.x - mean) * rs, 0.f); a.y = fmaxf((a.y - mean) * rs, 0.f);
    a.z = fmaxf((a.z - mean) * rs, 0.f); a.w = fmaxf((a.w - mean) * rs, 0.f);
    c.x = fmaxf((c.x - mean) * rs, 0.f); c.y = fmaxf((c.y - mean) * rs, 0.f);
    c.z = fmaxf((c.z - mean) * rs, 0.f); c.w = fmaxf((c.w - mean) * rs, 0.f);
    if (WRITE) {
        *(float4*)(Y + base)     = a;
        *(float4*)(Y + base + 4) = c;
    }
    float mx = fmaxf(fmaxf(fmaxf(a.x, a.y), fmaxf(a.z, a.w)),
                     fmaxf(fmaxf(c.x, c.y), fmaxf(c.z, c.w)));
    float smv = ((a.x + a.y) + (a.z + a.w)) + ((c.x + c.y) + (c.z + c.w));
    mx = fmaxf(mx, __shfl_xor_sync(0xffffffffu, mx, 1));
    mx = fmaxf(mx, __shfl_xor_sync(0xffffffffu, mx, 2));
    if ((lane & 3) == 0) rawmax[(size_t)bo * M + m] = mx;
#pragma unroll
    for (int o = 16; o; o >>= 1) smv += __shfl_down_sync(0xffffffffu, smv, o);
    if (lane == 0) swarp[warp] = smv;
    __syncthreads();
    if (threadIdx.x == 0) {
        float tt = 0.f;
        for (int w = 0; w < 8; w++) tt += swarp[w];
        atomicAdd(&xsum[bo], tt);
    }
}

// ============================================================================
// Channel attention gate
// ============================================================================
__global__ void gate_kernel(const float* __restrict__ xsum,
                            const float* __restrict__ w1,
                            const float* __restrict__ w2,
                            float* __restrict__ gate,
                            int O, int H, float invNMK) {
    __shared__ float s[384];
    __shared__ float h[96];
    int b = blockIdx.x, t = threadIdx.x;
    s[t] = xsum[b * O + t] * invNMK;
    __syncthreads();
    if (t < H) {
        float a = 0.f;
        for (int o = 0; o < O; o++) a += s[o] * w1[t * O + o];
        h[t] = fmaxf(a, 0.f);
    }
    __syncthreads();
    float a = 0.f;
    for (int j = 0; j < H; j++) a += h[j] * w2[t * H + j];
    gate[b * O + t] = 1.f / (1.f + expf(-a));
}

__global__ void scale_w_kernel(const float* __restrict__ W,
                               const float* __restrict__ gate,
                               float* __restrict__ Wa, float* __restrict__ Wb,
                               int O, int C) {
    int idx = blockIdx.x * blockDim.x + threadIdx.x;
    int total = B_ * O * C;
    if (idx >= total) return;
    int b = idx / (O * C);
    int r = idx % (O * C);
    int o = r / C, i = r % C;
    float g = gate[b * C + i];
    Wa[idx] = W[(size_t)o * (2 * C) + i] * g;
    Wb[idx] = W[(size_t)o * (2 * C) + C + i] * g;
}

__global__ void fout_kernel(const float* __restrict__ gate,
                            const float* __restrict__ rawmax,
                            float* __restrict__ f1, float* __restrict__ out,
                            int M, int total) {
    int i = blockIdx.x * blockDim.x + threadIdx.x;
    if (i >= total) return;
    int bo = i / M;
    float v = gate[bo] * rawmax[i];
    if (f1) f1[i] = v;
    out[i] = v;
}

// ============================================================================
// Host
// ============================================================================
extern "C" void kernel_launch(void* const* d_in, const int* in_sizes, int n_in,
                              void* d_out, int out_size) {
    const float* p      = (const float*)d_in[0];
    const float* f      = (const float*)d_in[1];
    const float* s0_w1  = (const float*)d_in[2];
    const float* s0_a1w1= (const float*)d_in[3];
    const float* s0_a1w2= (const float*)d_in[4];
    const float* s0_w2  = (const float*)d_in[5];
    const float* s0_a2w1= (const float*)d_in[6];
    const float* s0_a2w2= (const float*)d_in[7];
    const float* s1_w1  = (const float*)d_in[8];
    const float* s1_a1w1= (const float*)d_in[9];
    const float* s1_a1w2= (const float*)d_in[10];
    const float* s1_w2  = (const float*)d_in[11];
    const float* s1_a2w1= (const float*)d_in[12];
    const float* s1_a2w2= (const float*)d_in[13];
    float* out = (float*)d_out;

    float *feat, *Y, *Y2, *cp1, *cp2, *stats, *xsum, *rm1, *rm2, *gate, *Wa, *Wb, *bias, *f1;
    int *idx1, *idx2, *gidx;
    cudaGetSymbolAddress((void**)&feat, g_feat);
    cudaGetSymbolAddress((void**)&Y,    g_Y);
    cudaGetSymbolAddress((void**)&Y2,   g_Y2);
    cudaGetSymbolAddress((void**)&idx1, g_idx1);
    cudaGetSymbolAddress((void**)&idx2, g_idx2);
    cudaGetSymbolAddress((void**)&gidx, g_gidx);
    cudaGetSymbolAddress((void**)&cp1,  g_cp1);
    cudaGetSymbolAddress((void**)&cp2,  g_cp2);
    cudaGetSymbolAddress((void**)&stats,g_stats);
    cudaGetSymbolAddress((void**)&xsum, g_xsum);
    cudaGetSymbolAddress((void**)&rm1,  g_rmax1);
    cudaGetSymbolAddress((void**)&rm2,  g_rmax2);
    cudaGetSymbolAddress((void**)&gate, g_gate);
    cudaGetSymbolAddress((void**)&Wa,   g_Wa);
    cudaGetSymbolAddress((void**)&Wb,   g_Wb);
    cudaGetSymbolAddress((void**)&bias, g_bias);
    cudaGetSymbolAddress((void**)&f1,   g_f1);

    cudaFuncSetAttribute(fps_kernel<8192, 2048, 1024>,
                         cudaFuncAttributeMaxDynamicSharedMemorySize, 8192 * 3 * 4);
    cudaFuncSetAttribute(fps_kernel<2048, 512, 256>,
                         cudaFuncAttributeMaxDynamicSharedMemorySize, 2048 * 3 * 4);

    const int N0 = 8192, M1 = 2048, M2 = 512;
    const int NMK0 = M1 * 32;
    const int NMK1 = M2 * 32;
    const float inv0 = 1.f / (float)NMK0;
    const float inv1 = 1.f / (float)NMK1;

    // -------------------- Stage 0 --------------------
    fps_kernel<8192, 2048, 1024><<<4, 1024, 8192 * 3 * 4>>>(p, idx1, cp1);
    ballquery_kernel<<<(B_ * M1) / 8, 256>>>(cp1, p, gidx, N0, M1);
    conv1s0_kernel<<<dim3(NMK0 / 256, B_), 256>>>(p, cp1, f, gidx, idx1, s0_w1, Y);
    stats_kernel<<<B_ * 192, 256>>>(Y, stats, xsum, NMK0);
    normalize_kernel<true><<<B_ * 192 * (M1 / 64), 256>>>(Y, stats, rm1, xsum, M1, inv0);
    gate_kernel<<<B_, 192>>>(xsum, s0_a1w1, s0_a1w2, gate, 192, 48, inv0);
    scale_w_kernel<<<(B_ * 192 * 192 + 255) / 256, 256>>>(s0_w2, gate, Wa, Wb, 192, 192);

    gemm_kernel<true, false><<<dim3(M1 / 128, 192 / 64, B_), 256>>>(
        Wa, rm1, bias, nullptr, 192, 192, M1);
    mma_gemm_kernel<true, true><<<dim3(NMK0 / 128, 192 / 64, B_), 256>>>(
        Wb, Y, Y2, bias, 192, 192, NMK0);
    stats_kernel<<<B_ * 192, 256>>>(Y2, stats, xsum, NMK0);
    normalize_kernel<false><<<B_ * 192 * (M1 / 64), 256>>>(Y2, stats, rm2, xsum, M1, inv0);
    gate_kernel<<<B_, 192>>>(xsum, s0_a2w1, s0_a2w2, gate, 192, 48, inv0);
    fout_kernel<<<(B_ * 192 * M1 + 255) / 256, 256>>>(
        gate, rm2, f1, out + 227328, M1, B_ * 192 * M1);

    // -------------------- Stage 1 --------------------
    fps_kernel<2048, 512, 256><<<4, 256, 2048 * 3 * 4>>>(cp1, idx2, cp2);
    ballquery_kernel<<<(B_ * M2) / 8, 256>>>(cp2, cp1, gidx, M1, M2);
    build_feat_kernel<<<dim3(M2, B_), 128>>>(cp1, cp2, f1, gidx, idx2, feat, M1, M2, 192);

    mma_gemm_kernel<false, false><<<dim3(NMK1 / 128, 384 / 64, B_), 256>>>(
        s1_w1, feat, Y, nullptr, 384, 195, NMK1);
    stats_kernel<<<B_ * 384, 256>>>(Y, stats, xsum, NMK1);
    normalize_kernel<true><<<B_ * 384 * (M2 / 64), 256>>>(Y, stats, rm1, xsum, M2, inv1);
    gate_kernel<<<B_, 384>>>(xsum, s1_a1w1, s1_a1w2, gate, 384, 96, inv1);
    scale_w_kernel<<<(B_ * 384 * 384 + 255) / 256, 256>>>(s1_w2, gate, Wa, Wb, 384, 384);

    gemm_kernel<true, false><<<dim3(M2 / 128, 384 / 64, B_), 256>>>(
        Wa, rm1, bias, nullptr, 384, 384, M2);
    mma_gemm_kernel<true, true><<<dim3(NMK1 / 128, 384 / 64, B_), 256>>>(
        Wb, Y, Y2, bias, 384, 384, NMK1);
    stats_kernel<<<B_ * 384, 256>>>(Y2, stats, xsum, NMK1);
    normalize_kernel<false><<<B_ * 384 * (M2 / 64), 256>>>(Y2, stats, rm2, xsum, M2, inv1);
    gate_kernel<<<B_, 384>>>(xsum, s1_a2w1, s1_a2w2, gate, 384, 96, inv1);
    fout_kernel<<<(B_ * 384 * M2 + 255) / 256, 256>>>(
        gate, rm2, nullptr, out + 1800192, M2, B_ * 384 * M2);

    // -------------------- passthrough outputs --------------------
    cudaMemcpyAsync(out + 0,      p,   (size_t)98304 * 4, cudaMemcpyDeviceToDevice);
    cudaMemcpyAsync(out + 98304,  cp1, (size_t)24576 * 4, cudaMemcpyDeviceToDevice);
    cudaMemcpyAsync(out + 122880, cp2, (size_t)6144 * 4,  cudaMemcpyDeviceToDevice);
    cudaMemcpyAsync(out + 129024, f,   (size_t)98304 * 4, cudaMemcpyDeviceToDevice);
}